// round 16
// baseline (speedup 1.0000x reference)
#include <cuda_runtime.h>
#include <cuda_bf16.h>
#include <math.h>
#include <stdint.h>

#define BB    2
#define SS    4096
#define HIDN  2048
#define HH    16
#define DD    128
#define HD    2048
#define CCH   64
#define NCH   64
#define BSN   8192
#define NBH   2048
#define QSCALE 0.08838834764831845f

// ---------------- fp32 scratch ------------------------------------------------
__device__ float d_qlin[BSN*HD];
__device__ float d_klin[BSN*HD];
__device__ float d_vlin[BSN*HD];
__device__ float d_qb [BSN*HD];
__device__ float d_kb [BSN*HD];
__device__ float d_vb [BSN*HD];
__device__ float d_gb [BSN*HD];
__device__ float d_gate[BSN*HD];
__device__ float d_core[BSN*HD];
__device__ float d_fga[BSN*384];
__device__ float d_beta[BSN*HH];
__device__ float d_w   [NBH*CCH*DD];
__device__ float d_tf  [NBH*CCH*CCH];
__device__ float d_attn[NBH*CCH*CCH];
__device__ float d_qg  [NBH*CCH*DD];
__device__ float d_kt  [NBH*CCH*DD];
__device__ float d_egl [NBH*DD];

// ---------------- bf16 hi/lo scratch -----------------------------------------
__device__ __nv_bfloat16 d_xh[BSN*HIDN],  d_xl[BSN*HIDN];
__device__ __nv_bfloat16 d_yh[BSN*HD],    d_yl[BSN*HD];
__device__ __nv_bfloat16 d_fah[BSN*DD],   d_fal[BSN*DD];
__device__ __nv_bfloat16 d_gah[BSN*DD],   d_gal[BSN*DD];
__device__ __nv_bfloat16 d_WqTh[HD*HIDN], d_WqTl[HD*HIDN];
__device__ __nv_bfloat16 d_WkTh[HD*HIDN], d_WkTl[HD*HIDN];
__device__ __nv_bfloat16 d_WvTh[HD*HIDN], d_WvTl[HD*HIDN];
__device__ __nv_bfloat16 d_WoTh[HIDN*HD], d_WoTl[HIDN*HD];
__device__ __nv_bfloat16 d_WfgTh[384*HIDN], d_WfgTl[384*HIDN];
__device__ __nv_bfloat16 d_WfbTh[HD*DD],  d_WfbTl[HD*DD];
__device__ __nv_bfloat16 d_WgbTh[HD*DD],  d_WgbTl[HD*DD];

// ---------------- warp-MMA helpers -------------------------------------------
__device__ __forceinline__ uint32_t smem_u32(const void* p) {
    uint32_t a;
    asm("{ .reg .u64 t; cvta.to.shared.u64 t, %1; cvt.u32.u64 %0, t; }"
        : "=r"(a) : "l"(p));
    return a;
}
__device__ __forceinline__ void ldsm4(uint32_t& r0, uint32_t& r1, uint32_t& r2,
                                      uint32_t& r3, uint32_t addr) {
    asm volatile("ldmatrix.sync.aligned.m8n8.x4.shared.b16 {%0,%1,%2,%3}, [%4];"
                 : "=r"(r0), "=r"(r1), "=r"(r2), "=r"(r3) : "r"(addr));
}
__device__ __forceinline__ void mma16816(float* c, const uint32_t* a,
                                         uint32_t b0, uint32_t b1) {
    asm volatile(
        "mma.sync.aligned.m16n8k16.row.col.f32.bf16.bf16.f32 "
        "{%0,%1,%2,%3}, {%4,%5,%6,%7}, {%8,%9}, {%0,%1,%2,%3};"
        : "+f"(c[0]), "+f"(c[1]), "+f"(c[2]), "+f"(c[3])
        : "r"(a[0]), "r"(a[1]), "r"(a[2]), "r"(a[3]), "r"(b0), "r"(b1));
}

// ---------------- HMMA bf16x3 GEMM: C(M,N) = A @ B^T -------------------------
// 128x128 CTA tile, 8 warps of 64x32, BK=64 (halved barrier/load phases).
// A: [M][K] bf16 hi/lo. B: [Npad>=N rows][K] bf16 hi/lo. C fp32 [M][N].
// Requires M%128==0, N%128==0, K%64==0.
#define SKA 72                         // padded K stride (elems) -> 144B rows
#define TCSZ (128*SKA*2)               // bytes per array (18432)
#define TCSMEM (4*TCSZ)                // total dynamic smem (73728)

__global__ __launch_bounds__(256) void tc_gemm(
    const __nv_bfloat16* __restrict__ Ah, const __nv_bfloat16* __restrict__ Al,
    const __nv_bfloat16* __restrict__ Bh, const __nv_bfloat16* __restrict__ Bl,
    float* __restrict__ C, int M, int N, int K)
{
    extern __shared__ __nv_bfloat16 smp[];
    char* smc = (char*)smp;
    const uint32_t smb = smem_u32(smp);

    const int tid  = threadIdx.x;
    const int wid  = tid >> 5, lane = tid & 31;
    const int row0 = blockIdx.y * 128, col0 = blockIdx.x * 128;
    const int wm   = wid >> 2, wn = wid & 3;     // warp 64x32 tile

    float acc[4][4][4];
    #pragma unroll
    for (int im = 0; im < 4; im++)
        #pragma unroll
        for (int in = 0; in < 4; in++)
            #pragma unroll
            for (int r = 0; r < 4; r++) acc[im][in][r] = 0.f;

    // global->smem: 2 threads per row, each loads 32 elems (4 x uint4) per array
    const int lr = tid >> 1, lk = (tid & 1) * 32;
    const __nv_bfloat16* gAh = Ah + (size_t)(row0 + lr) * K + lk;
    const __nv_bfloat16* gAl = Al + (size_t)(row0 + lr) * K + lk;
    const __nv_bfloat16* gBh = Bh + (size_t)(col0 + lr) * K + lk;
    const __nv_bfloat16* gBl = Bl + (size_t)(col0 + lr) * K + lk;
    char* pAh = smc +          (lr * SKA + lk) * 2;
    char* pAl = smc + TCSZ   + (lr * SKA + lk) * 2;
    char* pBh = smc + 2*TCSZ + (lr * SKA + lk) * 2;
    char* pBl = smc + 3*TCSZ + (lr * SKA + lk) * 2;

    const uint32_t uAh = smb, uAl = smb + TCSZ, uBh = smb + 2*TCSZ, uBl = smb + 3*TCSZ;
    const int aRow = wm * 64 + (lane & 15);
    const int aCol = (lane >> 4) * 8;
    const int bRow = wn * 32 + ((lane >> 3) & 1) * 8 + (lane & 7);
    const int bCol = (lane >> 4) * 8;

    for (int k0 = 0; k0 < K; k0 += 64) {
        __syncthreads();
        #pragma unroll
        for (int c = 0; c < 4; c++) {
            *(uint4*)(pAh + c * 16) = *(const uint4*)(gAh + c * 8);
            *(uint4*)(pAl + c * 16) = *(const uint4*)(gAl + c * 8);
            *(uint4*)(pBh + c * 16) = *(const uint4*)(gBh + c * 8);
            *(uint4*)(pBl + c * 16) = *(const uint4*)(gBl + c * 8);
        }
        gAh += 64; gAl += 64; gBh += 64; gBl += 64;
        __syncthreads();

        #pragma unroll
        for (int ks = 0; ks < 64; ks += 16) {
            uint32_t afh[4][4], afl[4][4];
            #pragma unroll
            for (int im = 0; im < 4; im++) {
                uint32_t off = ((aRow + im * 16) * SKA + ks + aCol) * 2;
                ldsm4(afh[im][0], afh[im][1], afh[im][2], afh[im][3], uAh + off);
                ldsm4(afl[im][0], afl[im][1], afl[im][2], afl[im][3], uAl + off);
            }
            uint32_t bfh[2][4], bfl[2][4];
            #pragma unroll
            for (int p = 0; p < 2; p++) {
                uint32_t off = ((bRow + p * 16) * SKA + ks + bCol) * 2;
                ldsm4(bfh[p][0], bfh[p][1], bfh[p][2], bfh[p][3], uBh + off);
                ldsm4(bfl[p][0], bfl[p][1], bfl[p][2], bfl[p][3], uBl + off);
            }
            #pragma unroll
            for (int im = 0; im < 4; im++) {
                #pragma unroll
                for (int in = 0; in < 4; in++) {
                    const int p = in >> 1, q = in & 1;
                    uint32_t bh0 = bfh[p][q], bh1 = bfh[p][2 + q];
                    uint32_t bl0 = bfl[p][q], bl1 = bfl[p][2 + q];
                    mma16816(acc[im][in], afh[im], bh0, bh1);
                    mma16816(acc[im][in], afh[im], bl0, bl1);
                    mma16816(acc[im][in], afl[im], bh0, bh1);
                }
            }
        }
    }

    const int cr = lane >> 2, cc = (lane & 3) * 2;
    #pragma unroll
    for (int im = 0; im < 4; im++) {
        #pragma unroll
        for (int in = 0; in < 4; in++) {
            int gm = row0 + wm * 64 + im * 16 + cr;
            int gn = col0 + wn * 32 + in * 8 + cc;
            float2 v0 = make_float2(acc[im][in][0], acc[im][in][1]);
            float2 v1 = make_float2(acc[im][in][2], acc[im][in][3]);
            *(float2*)(C + (size_t)gm * N + gn)       = v0;
            *(float2*)(C + (size_t)(gm + 8) * N + gn) = v1;
        }
    }
}

// ---------------- fp32 -> bf16 hi/lo split -----------------------------------
__global__ void split_bf16(const float* __restrict__ in,
                           __nv_bfloat16* __restrict__ hi,
                           __nv_bfloat16* __restrict__ lo, int n)
{
    int i = blockIdx.x * 256 + threadIdx.x;
    if (i < n) {
        float a = in[i];
        __nv_bfloat16 h = __float2bfloat16(a);
        hi[i] = h;
        lo[i] = __float2bfloat16(a - __bfloat162float(h));
    }
}

// ---------------- transpose + split: W[K][N] -> WT hi/lo [rows][K] -----------
__global__ void tsplit_kernel(const float* __restrict__ W,
                              __nv_bfloat16* __restrict__ hi,
                              __nv_bfloat16* __restrict__ lo,
                              int K, int N, int Npad)
{
    __shared__ float t[32][33];
    int kb = blockIdx.x * 32, nb = blockIdx.y * 32;
    int tx = threadIdx.x, ty = threadIdx.y;
    #pragma unroll
    for (int i = 0; i < 4; i++) {
        int k = kb + ty + i * 8;
        int n = nb + tx;
        t[ty + i * 8][tx] = (n < N) ? W[(size_t)k * N + n] : 0.f;
    }
    __syncthreads();
    #pragma unroll
    for (int i = 0; i < 4; i++) {
        int n = nb + ty + i * 8;
        int k = kb + tx;
        float a = t[tx][ty + i * 8];
        __nv_bfloat16 h = __float2bfloat16(a);
        hi[(size_t)n * K + k] = h;
        lo[(size_t)n * K + k] = __float2bfloat16(a - __bfloat162float(h));
    }
}

// ---------------- unpack fused fga GEMM output -------------------------------
// fga: [BSN][384] = [fa(128) | ga(128) | betaraw(16 valid of 128)]
__global__ void unpack_fga(const float* __restrict__ fga,
                           __nv_bfloat16* __restrict__ fah, __nv_bfloat16* __restrict__ fal,
                           __nv_bfloat16* __restrict__ gah, __nv_bfloat16* __restrict__ gal,
                           float* __restrict__ beta)
{
    int i = blockIdx.x * 256 + threadIdx.x;
    if (i >= BSN * 384) return;
    int m = i / 384, c = i - m * 384;
    float v = fga[i];
    if (c < 128) {
        __nv_bfloat16 h = __float2bfloat16(v);
        fah[m * 128 + c] = h;
        fal[m * 128 + c] = __float2bfloat16(v - __bfloat162float(h));
    } else if (c < 256) {
        __nv_bfloat16 h = __float2bfloat16(v);
        gah[m * 128 + c - 128] = h;
        gal[m * 128 + c - 128] = __float2bfloat16(v - __bfloat162float(h));
    } else if (c < 272) {
        beta[m * 16 + (c - 256)] = 1.f / (1.f + __expf(-v));
    }
}

// ---------------- causal depthwise conv (KC=4) + SiLU + optional l2norm ------
__global__ void conv_silu_kernel(const float* __restrict__ lin,
                                 const float* __restrict__ kern,
                                 float* __restrict__ outp, int do_l2)
{
    int tok = blockIdx.x;
    int h   = blockIdx.y;
    int d   = threadIdx.x;
    int t   = tok & (SS - 1);
    int c   = h * DD + d;

    float acc = 0.f;
    #pragma unroll
    for (int j = 0; j < 4; j++) {
        int tt = t - 3 + j;
        if (tt >= 0) acc += lin[(size_t)(tok - 3 + j) * HD + c] * kern[j * HD + c];
    }
    float y = acc / (1.f + __expf(-acc));

    if (do_l2) {
        float ss = y * y;
        #pragma unroll
        for (int off = 16; off; off >>= 1) ss += __shfl_xor_sync(0xffffffffu, ss, off);
        __shared__ float wsum[4];
        if ((d & 31) == 0) wsum[d >> 5] = ss;
        __syncthreads();
        float tot = wsum[0] + wsum[1] + wsum[2] + wsum[3];
        y *= rsqrtf(tot + 1e-6f);
    }
    outp[(size_t)tok * HD + c] = y;
}

// ---------------- g = -exp(A_log[h]) * softplus(g_lin + dt_bias) -------------
__global__ void g_transform_kernel(float* __restrict__ g,
                                   const float* __restrict__ A_log,
                                   const float* __restrict__ dt_bias)
{
    int i = blockIdx.x * 256 + threadIdx.x;
    if (i >= BSN * HD) return;
    int c = i & (HD - 1);
    float xv = g[i] + dt_bias[c];
    float sp = (xv > 20.f) ? xv : log1pf(__expf(xv));
    g[i] = -__expf(A_log[c >> 7]) * sp;
}

// ---------------- per-chunk precompute ---------------------------------------
__global__ __launch_bounds__(256) void precompute_kernel(
    const float* __restrict__ qv, const float* __restrict__ kv,
    const float* __restrict__ gv, const float* __restrict__ betav,
    float* __restrict__ w_g, float* __restrict__ tf_g,
    float* __restrict__ attn_g, float* __restrict__ qg_g,
    float* __restrict__ kt_g, float* __restrict__ egl_g)
{
    const int n  = blockIdx.x;
    const int bh = blockIdx.y;
    const int b  = bh >> 4;
    const int h  = bh & 15;
    const int tid = threadIdx.x;
    const int chIdx = bh * NCH + n;
    const size_t baseTok = (size_t)b * SS + n * CCH;

    extern __shared__ float sm[];
    float* sk = sm;                    // 8192
    float* sg = sm + 8192;             // 8192
    float* sA = sm + 16384;            // 64*65
    float* sT = sA + 64 * 65;          // 64*65
    float* sb = sT + 64 * 65;          // 64

    for (int l = tid; l < 8192; l += 256) {
        int i = l >> 7, d = l & 127;
        size_t gi = ((baseTok + i) * HH + h) * DD + d;
        sk[l] = kv[gi];
        sg[l] = gv[gi];
    }
    if (tid < 64) sb[tid] = betav[(baseTok + tid) * HH + h];
    __syncthreads();

    if (tid < 128) {
        float acc = sg[tid];
        for (int i = 1; i < 64; i++) { acc += sg[i * 128 + tid]; sg[i * 128 + tid] = acc; }
    }
    for (int l = tid; l < 4096; l += 256) {
        int i2 = l >> 6, j2 = l & 63;
        if (j2 > i2) attn_g[(size_t)chIdx * 4096 + l] = 0.f;
    }
    __syncthreads();

    {
        const int i   = tid >> 2;
        const int cch = tid & 3;
        const int d0  = cch * 32;
        float qreg[32], kreg[32], greg[32];
        const float* qp = qv + ((baseTok + i) * HH + h) * DD + d0;
        #pragma unroll
        for (int d = 0; d < 32; d++) {
            qreg[d] = __ldg(qp + d);
            kreg[d] = sk[i * 128 + d0 + d];
            greg[d] = sg[i * 128 + d0 + d];
        }
        const unsigned lane = tid & 31;
        const unsigned gmask = 0xFu << (lane & ~3u);
        const size_t aoff = (size_t)chIdx * 4096 + i * 64;
        for (int j = 0; j <= i; j++) {
            float aA = 0.f, aQ = 0.f;
            const float* skj = sk + j * 128 + d0;
            const float* sgj = sg + j * 128 + d0;
            #pragma unroll
            for (int d = 0; d < 32; d++) {
                float e  = __expf(greg[d] - sgj[d]);
                float kk = e * skj[d];
                aQ += kk * qreg[d];
                aA += kk * kreg[d];
            }
            aA += __shfl_down_sync(gmask, aA, 1, 4);
            aA += __shfl_down_sync(gmask, aA, 2, 4);
            aQ += __shfl_down_sync(gmask, aQ, 1, 4);
            aQ += __shfl_down_sync(gmask, aQ, 2, 4);
            if (cch == 0) {
                attn_g[aoff + j] = aQ * QSCALE;
                if (j < i) sA[i * 65 + j] = aA * sb[i];
            }
        }
    }
    __syncthreads();

    for (int l = tid; l < 64 * 65; l += 256) sT[l] = 0.f;
    __syncthreads();
    if (tid < 64) sT[tid * 65 + tid] = 1.f;
    __syncthreads();
    for (int ii = 1; ii < 64; ii++) {
        if (tid < ii) {
            int j = tid;
            float s = sA[ii * 65 + j];
            for (int m = j + 1; m < ii; m++) s += sA[ii * 65 + m] * sT[m * 65 + j];
            sT[ii * 65 + j] = -s;
        }
        __syncthreads();
    }
    for (int l = tid; l < 4096; l += 256) {
        int i2 = l >> 6, j2 = l & 63;
        sT[i2 * 65 + j2] *= sb[j2];
    }
    __syncthreads();
    for (int l = tid; l < 4096; l += 256)
        tf_g[(size_t)chIdx * 4096 + l] = sT[(l >> 6) * 65 + (l & 63)];

    if (tid < 128) egl_g[(size_t)chIdx * 128 + tid] = __expf(sg[63 * 128 + tid]);
    for (int l = tid; l < 8192; l += 256) {
        int i2 = l >> 7, d = l & 127;
        float gl = sg[63 * 128 + d];
        float gi = sg[l];
        kt_g[(size_t)chIdx * 8192 + l] = sk[l] * __expf(gl - gi);
        size_t qidx = ((baseTok + i2) * HH + h) * DD + d;
        qg_g[(size_t)chIdx * 8192 + l] = __ldg(qv + qidx) * __expf(gi) * QSCALE;
    }
    __syncthreads();
    for (int l = tid; l < 8192; l += 256) sk[l] *= __expf(sg[l]);
    __syncthreads();

    {
        const int ig  = tid >> 4;
        const int dg  = tid & 15;
        const int i0  = ig * 4;
        const int dd0 = dg * 8;
        float acc[4][8];
        #pragma unroll
        for (int r = 0; r < 4; r++)
            #pragma unroll
            for (int d = 0; d < 8; d++) acc[r][d] = 0.f;
        for (int j = 0; j < 64; j++) {
            float t0 = sT[(i0 + 0) * 65 + j];
            float t1 = sT[(i0 + 1) * 65 + j];
            float t2 = sT[(i0 + 2) * 65 + j];
            float t3 = sT[(i0 + 3) * 65 + j];
            #pragma unroll
            for (int d = 0; d < 8; d++) {
                float kvv = sk[j * 128 + dd0 + d];
                acc[0][d] += t0 * kvv;
                acc[1][d] += t1 * kvv;
                acc[2][d] += t2 * kvv;
                acc[3][d] += t3 * kvv;
            }
        }
        #pragma unroll
        for (int r = 0; r < 4; r++)
            #pragma unroll
            for (int d = 0; d < 8; d++)
                w_g[(size_t)chIdx * 8192 + (i0 + r) * 128 + dd0 + d] = acc[r][d];
    }
}

// ---------------- sequential chunk scan, split over dv (tiles of 16) ---------
__global__ __launch_bounds__(256) void scan_kernel(
    const float* __restrict__ vv, const float* __restrict__ w_g,
    const float* __restrict__ tf_g, const float* __restrict__ attn_g,
    const float* __restrict__ qg_g, const float* __restrict__ kt_g,
    const float* __restrict__ egl_g, float* __restrict__ core)
{
    const int blk = blockIdx.x;
    const int bh  = blk >> 3;
    const int b   = bh >> 4, h = bh & 15;
    const int e0  = (blk & 7) * 16;
    const int tid = threadIdx.x;
    const int e   = tid & 15;
    const int cb  = tid >> 4;

    extern __shared__ float sm[];
    float* sS = sm;            // 128*16
    float* sV = sm + 2048;     // 64*16
    float* sU = sm + 3072;     // 64*16
    float* sM = sm + 4096;     // 64*64
    float* sW = sm + 8192;     // 64*128
    float* sE = sm + 16384;    // 128

    for (int l = tid; l < 2048; l += 256) sS[l] = 0.f;

    for (int n = 0; n < NCH; n++) {
        const size_t ch = (size_t)bh * NCH + n;
        const size_t tokBase = (size_t)b * SS + n * CCH;
        __syncthreads();
        for (int l = tid; l < 1024; l += 256) {
            int c = l >> 4, ee = l & 15;
            sV[l] = vv[((tokBase + c) * HH + h) * DD + e0 + ee];
        }
        for (int l = tid; l < 4096; l += 256) sM[l] = tf_g[ch * 4096 + l];
        __syncthreads();
        float a0 = 0, a1 = 0, a2 = 0, a3 = 0;
        for (int j = 0; j < 64; j++) {
            float vj = sV[j * 16 + e];
            a0 += sM[(cb     ) * 64 + j] * vj;
            a1 += sM[(cb + 16) * 64 + j] * vj;
            a2 += sM[(cb + 32) * 64 + j] * vj;
            a3 += sM[(cb + 48) * 64 + j] * vj;
        }
        __syncthreads();
        for (int l = tid; l < 8192; l += 256) sW[l] = w_g[ch * 8192 + l];
        __syncthreads();
        for (int d = 0; d < 128; d++) {
            float sd = sS[d * 16 + e];
            a0 -= sW[(cb     ) * 128 + d] * sd;
            a1 -= sW[(cb + 16) * 128 + d] * sd;
            a2 -= sW[(cb + 32) * 128 + d] * sd;
            a3 -= sW[(cb + 48) * 128 + d] * sd;
        }
        sU[(cb     ) * 16 + e] = a0;
        sU[(cb + 16) * 16 + e] = a1;
        sU[(cb + 32) * 16 + e] = a2;
        sU[(cb + 48) * 16 + e] = a3;
        __syncthreads();
        for (int l = tid; l < 4096; l += 256) sM[l] = attn_g[ch * 4096 + l];
        for (int l = tid; l < 8192; l += 256) sW[l] = qg_g[ch * 8192 + l];
        __syncthreads();
        float o0 = 0, o1 = 0, o2 = 0, o3 = 0;
        for (int j = 0; j < 64; j++) {
            float uj = sU[j * 16 + e];
            o0 += sM[(cb     ) * 64 + j] * uj;
            o1 += sM[(cb + 16) * 64 + j] * uj;
            o2 += sM[(cb + 32) * 64 + j] * uj;
            o3 += sM[(cb + 48) * 64 + j] * uj;
        }
        for (int d = 0; d < 128; d++) {
            float sd = sS[d * 16 + e];
            o0 += sW[(cb     ) * 128 + d] * sd;
            o1 += sW[(cb + 16) * 128 + d] * sd;
            o2 += sW[(cb + 32) * 128 + d] * sd;
            o3 += sW[(cb + 48) * 128 + d] * sd;
        }
        core[((tokBase + cb     ) * HH + h) * DD + e0 + e] = o0;
        core[((tokBase + cb + 16) * HH + h) * DD + e0 + e] = o1;
        core[((tokBase + cb + 32) * HH + h) * DD + e0 + e] = o2;
        core[((tokBase + cb + 48) * HH + h) * DD + e0 + e] = o3;
        __syncthreads();
        for (int l = tid; l < 8192; l += 256) sW[l] = kt_g[ch * 8192 + l];
        if (tid < 128) sE[tid] = egl_g[ch * 128 + tid];
        __syncthreads();
        float sacc[8];
        #pragma unroll
        for (int r = 0; r < 8; r++) sacc[r] = sE[cb + 16 * r] * sS[(cb + 16 * r) * 16 + e];
        for (int c = 0; c < 64; c++) {
            float u = sU[c * 16 + e];
            #pragma unroll
            for (int r = 0; r < 8; r++) sacc[r] += sW[c * 128 + cb + 16 * r] * u;
        }
        #pragma unroll
        for (int r = 0; r < 8; r++) sS[(cb + 16 * r) * 16 + e] = sacc[r];
    }
}

// ---------------- RMS norm * sigmoid(gate + bgb) -> bf16 hi/lo ---------------
__global__ void rmsgate_kernel(const float* __restrict__ core,
                               const float* __restrict__ gate,
                               const float* __restrict__ bgb,
                               const float* __restrict__ rms_scale,
                               __nv_bfloat16* __restrict__ yh,
                               __nv_bfloat16* __restrict__ yl)
{
    int tok = blockIdx.x, h = blockIdx.y, d = threadIdx.x;
    int c = h * DD + d;
    size_t i = (size_t)tok * HD + c;
    float cf = core[i];
    float ss = cf * cf;
    #pragma unroll
    for (int off = 16; off; off >>= 1) ss += __shfl_xor_sync(0xffffffffu, ss, off);
    __shared__ float ws[4];
    if ((d & 31) == 0) ws[d >> 5] = ss;
    __syncthreads();
    float tot = ws[0] + ws[1] + ws[2] + ws[3];
    float normed = cf * rsqrtf(tot * (1.f / 128.f) + 1e-5f) * rms_scale[d];
    float gt = gate[i] + bgb[c];
    float o = normed / (1.f + __expf(-gt));
    __nv_bfloat16 hh = __float2bfloat16(o);
    yh[i] = hh;
    yl[i] = __float2bfloat16(o - __bfloat162float(hh));
}

// ---------------- launch ------------------------------------------------------
extern "C" void kernel_launch(void* const* d_in, const int* in_sizes, int n_in,
                              void* d_out, int out_size)
{
    const float* x      = (const float*)d_in[0];
    const float* Wq     = (const float*)d_in[1];
    const float* Wk     = (const float*)d_in[2];
    const float* Wv     = (const float*)d_in[3];
    const float* convq  = (const float*)d_in[4];
    const float* convk  = (const float*)d_in[5];
    const float* convv  = (const float*)d_in[6];
    const float* Wb     = (const float*)d_in[7];
    const float* Wfa    = (const float*)d_in[8];
    const float* Wfb    = (const float*)d_in[9];
    const float* Wga    = (const float*)d_in[10];
    const float* Wgb    = (const float*)d_in[11];
    const float* bgb    = (const float*)d_in[12];
    const float* A_log  = (const float*)d_in[13];
    const float* dt_bias= (const float*)d_in[14];
    const float* rms_sc = (const float*)d_in[15];
    const float* Wo     = (const float*)d_in[16];
    float* outp = (float*)d_out;

    float *qlin, *klin, *vlin, *qb, *kb, *vb, *gb, *gate, *core, *fga, *beta;
    float *wg, *tfg, *attng, *qgg, *ktg, *eglg;
    __nv_bfloat16 *xh, *xl, *yh, *yl, *fah, *fal, *gah, *gal;
    __nv_bfloat16 *WqTh, *WqTl, *WkTh, *WkTl, *WvTh, *WvTl, *WoTh, *WoTl;
    __nv_bfloat16 *WfgTh, *WfgTl, *WfbTh, *WfbTl, *WgbTh, *WgbTl;

    cudaGetSymbolAddress((void**)&qlin, d_qlin);
    cudaGetSymbolAddress((void**)&klin, d_klin);
    cudaGetSymbolAddress((void**)&vlin, d_vlin);
    cudaGetSymbolAddress((void**)&qb,   d_qb);
    cudaGetSymbolAddress((void**)&kb,   d_kb);
    cudaGetSymbolAddress((void**)&vb,   d_vb);
    cudaGetSymbolAddress((void**)&gb,   d_gb);
    cudaGetSymbolAddress((void**)&gate, d_gate);
    cudaGetSymbolAddress((void**)&core, d_core);
    cudaGetSymbolAddress((void**)&fga,  d_fga);
    cudaGetSymbolAddress((void**)&beta, d_beta);
    cudaGetSymbolAddress((void**)&wg,   d_w);
    cudaGetSymbolAddress((void**)&tfg,  d_tf);
    cudaGetSymbolAddress((void**)&attng,d_attn);
    cudaGetSymbolAddress((void**)&qgg,  d_qg);
    cudaGetSymbolAddress((void**)&ktg,  d_kt);
    cudaGetSymbolAddress((void**)&eglg, d_egl);
    cudaGetSymbolAddress((void**)&xh, d_xh);   cudaGetSymbolAddress((void**)&xl, d_xl);
    cudaGetSymbolAddress((void**)&yh, d_yh);   cudaGetSymbolAddress((void**)&yl, d_yl);
    cudaGetSymbolAddress((void**)&fah, d_fah); cudaGetSymbolAddress((void**)&fal, d_fal);
    cudaGetSymbolAddress((void**)&gah, d_gah); cudaGetSymbolAddress((void**)&gal, d_gal);
    cudaGetSymbolAddress((void**)&WqTh, d_WqTh); cudaGetSymbolAddress((void**)&WqTl, d_WqTl);
    cudaGetSymbolAddress((void**)&WkTh, d_WkTh); cudaGetSymbolAddress((void**)&WkTl, d_WkTl);
    cudaGetSymbolAddress((void**)&WvTh, d_WvTh); cudaGetSymbolAddress((void**)&WvTl, d_WvTl);
    cudaGetSymbolAddress((void**)&WoTh, d_WoTh); cudaGetSymbolAddress((void**)&WoTl, d_WoTl);
    cudaGetSymbolAddress((void**)&WfgTh, d_WfgTh); cudaGetSymbolAddress((void**)&WfgTl, d_WfgTl);
    cudaGetSymbolAddress((void**)&WfbTh, d_WfbTh); cudaGetSymbolAddress((void**)&WfbTl, d_WfbTl);
    cudaGetSymbolAddress((void**)&WgbTh, d_WgbTh); cudaGetSymbolAddress((void**)&WgbTl, d_WgbTl);

    const size_t preSmem  = 24768 * sizeof(float);
    const size_t scanSmem = 16512 * sizeof(float);
    cudaFuncSetAttribute(precompute_kernel, cudaFuncAttributeMaxDynamicSharedMemorySize, (int)preSmem);
    cudaFuncSetAttribute(scan_kernel,       cudaFuncAttributeMaxDynamicSharedMemorySize, (int)scanSmem);
    cudaFuncSetAttribute(tc_gemm,           cudaFuncAttributeMaxDynamicSharedMemorySize, TCSMEM);

    dim3 blk256(256);
    dim3 tblk(32, 8);

    // launches 1-5: prerequisites; launch 6 = big GEMM (ncu -s 5 -c 1 target)
    split_bf16<<<(BSN * HIDN) / 256, blk256>>>(x, xh, xl, BSN * HIDN);                  // 1
    tsplit_kernel<<<dim3(HIDN / 32, HD / 32), tblk>>>(Wq, WqTh, WqTl, HIDN, HD, HD);    // 2
    tsplit_kernel<<<dim3(HIDN / 32, HD / 32), tblk>>>(Wk, WkTh, WkTl, HIDN, HD, HD);    // 3
    tsplit_kernel<<<dim3(HIDN / 32, HD / 32), tblk>>>(Wv, WvTh, WvTl, HIDN, HD, HD);    // 4
    tsplit_kernel<<<dim3(HD / 32, HIDN / 32), tblk>>>(Wo, WoTh, WoTl, HD, HIDN, HIDN);  // 5
    tc_gemm<<<dim3(16, 64), 256, TCSMEM>>>(xh, xl, WqTh, WqTl, qlin, BSN, HD, HIDN);    // 6
    tc_gemm<<<dim3(16, 64), 256, TCSMEM>>>(xh, xl, WkTh, WkTl, klin, BSN, HD, HIDN);
    tc_gemm<<<dim3(16, 64), 256, TCSMEM>>>(xh, xl, WvTh, WvTl, vlin, BSN, HD, HIDN);

    // fused fa/ga/beta projection
    tsplit_kernel<<<dim3(HIDN / 32, 4), tblk>>>(Wfa, WfgTh,              WfgTl,              HIDN, DD, 128);
    tsplit_kernel<<<dim3(HIDN / 32, 4), tblk>>>(Wga, WfgTh + 128 * HIDN, WfgTl + 128 * HIDN, HIDN, DD, 128);
    tsplit_kernel<<<dim3(HIDN / 32, 4), tblk>>>(Wb,  WfgTh + 256 * HIDN, WfgTl + 256 * HIDN, HIDN, HH, 128);
    tc_gemm<<<dim3(3, 64), 256, TCSMEM>>>(xh, xl, WfgTh, WfgTl, fga, BSN, 384, HIDN);
    unpack_fga<<<(BSN * 384) / 256, blk256>>>(fga, fah, fal, gah, gal, beta);

    // conv + silu (+ l2norm for q,k)
    conv_silu_kernel<<<dim3(BSN, HH), 128>>>(qlin, convq, qb, 1);
    conv_silu_kernel<<<dim3(BSN, HH), 128>>>(klin, convk, kb, 1);
    conv_silu_kernel<<<dim3(BSN, HH), 128>>>(vlin, convv, vb, 0);

    // second-stage projections
    tsplit_kernel<<<dim3(DD / 32, HD / 32), tblk>>>(Wfb, WfbTh, WfbTl, DD, HD, HD);
    tsplit_kernel<<<dim3(DD / 32, HD / 32), tblk>>>(Wgb, WgbTh, WgbTl, DD, HD, HD);
    tc_gemm<<<dim3(16, 64), 256, TCSMEM>>>(fah, fal, WfbTh, WfbTl, gb, BSN, HD, DD);
    tc_gemm<<<dim3(16, 64), 256, TCSMEM>>>(gah, gal, WgbTh, WgbTl, gate, BSN, HD, DD);
    g_transform_kernel<<<(BSN * HD) / 256, blk256>>>(gb, A_log, dt_bias);

    // chunked delta rule
    precompute_kernel<<<dim3(NCH, BB * HH), blk256, preSmem>>>(
        qb, kb, gb, beta, wg, tfg, attng, qgg, ktg, eglg);
    scan_kernel<<<dim3(BB * HH * 8), blk256, scanSmem>>>(
        vb, wg, tfg, attng, qgg, ktg, eglg, core);

    // rmsnorm * gate -> bf16 hi/lo, final projection
    rmsgate_kernel<<<dim3(BSN, HH), 128>>>(core, gate, bgb, rms_sc, yh, yl);
    tc_gemm<<<dim3(16, 64), 256, TCSMEM>>>(yh, yl, WoTh, WoTl, outp, BSN, HIDN, HD);
}

// round 17
// speedup vs baseline: 1.1015x; 1.1015x over previous
#include <cuda_runtime.h>
#include <cuda_bf16.h>
#include <math.h>
#include <stdint.h>

#define BB    2
#define SS    4096
#define HIDN  2048
#define HH    16
#define DD    128
#define HD    2048
#define CCH   64
#define NCH   64
#define BSN   8192
#define NBH   2048
#define NQKV  6528            // 2048*3 + 128 + 128 + 128(pad)
#define QSCALE 0.08838834764831845f

// ---------------- fp32 scratch ------------------------------------------------
__device__ float d_qkv[BSN*NQKV];          // fused x-projection output
__device__ float d_qb [BSN*HD];
__device__ float d_kb [BSN*HD];
__device__ float d_vb [BSN*HD];
__device__ float d_gb [BSN*HD];
__device__ float d_gate[BSN*HD];
__device__ float d_core[BSN*HD];
__device__ float d_beta[BSN*HH];
__device__ float d_w   [NBH*CCH*DD];
__device__ float d_tf  [NBH*CCH*CCH];
__device__ float d_attn[NBH*CCH*CCH];
__device__ float d_qg  [NBH*CCH*DD];
__device__ float d_kt  [NBH*CCH*DD];
__device__ float d_egl [NBH*DD];

// ---------------- bf16 hi/lo scratch -----------------------------------------
__device__ __nv_bfloat16 d_xh[BSN*HIDN],  d_xl[BSN*HIDN];
__device__ __nv_bfloat16 d_yh[BSN*HD],    d_yl[BSN*HD];
__device__ __nv_bfloat16 d_fah[BSN*DD],   d_fal[BSN*DD];
__device__ __nv_bfloat16 d_gah[BSN*DD],   d_gal[BSN*DD];
__device__ __nv_bfloat16 d_WxTh[NQKV*HIDN], d_WxTl[NQKV*HIDN];   // fused weights
__device__ __nv_bfloat16 d_WoTh[HIDN*HD], d_WoTl[HIDN*HD];
__device__ __nv_bfloat16 d_WfbTh[HD*DD],  d_WfbTl[HD*DD];
__device__ __nv_bfloat16 d_WgbTh[HD*DD],  d_WgbTl[HD*DD];

// ---------------- warp-MMA helpers -------------------------------------------
__device__ __forceinline__ uint32_t smem_u32(const void* p) {
    uint32_t a;
    asm("{ .reg .u64 t; cvta.to.shared.u64 t, %1; cvt.u32.u64 %0, t; }"
        : "=r"(a) : "l"(p));
    return a;
}
__device__ __forceinline__ void ldsm4(uint32_t& r0, uint32_t& r1, uint32_t& r2,
                                      uint32_t& r3, uint32_t addr) {
    asm volatile("ldmatrix.sync.aligned.m8n8.x4.shared.b16 {%0,%1,%2,%3}, [%4];"
                 : "=r"(r0), "=r"(r1), "=r"(r2), "=r"(r3) : "r"(addr));
}
__device__ __forceinline__ void mma16816(float* c, const uint32_t* a,
                                         uint32_t b0, uint32_t b1) {
    asm volatile(
        "mma.sync.aligned.m16n8k16.row.col.f32.bf16.bf16.f32 "
        "{%0,%1,%2,%3}, {%4,%5,%6,%7}, {%8,%9}, {%0,%1,%2,%3};"
        : "+f"(c[0]), "+f"(c[1]), "+f"(c[2]), "+f"(c[3])
        : "r"(a[0]), "r"(a[1]), "r"(a[2]), "r"(a[3]), "r"(b0), "r"(b1));
}

// ---------------- HMMA bf16x3 GEMM (R14 best config, unchanged) --------------
// C(M,N) = A @ B^T. Tile 128x128, 8 warps of 64x32, BK=32, static smem.
// Requires M%128==0, N%128==0, K%32==0.
#define SKA 40

__global__ __launch_bounds__(256) void tc_gemm(
    const __nv_bfloat16* __restrict__ Ah, const __nv_bfloat16* __restrict__ Al,
    const __nv_bfloat16* __restrict__ Bh, const __nv_bfloat16* __restrict__ Bl,
    float* __restrict__ C, int M, int N, int K)
{
    __shared__ __nv_bfloat16 sAh[128*SKA], sAl[128*SKA];
    __shared__ __nv_bfloat16 sBh[128*SKA], sBl[128*SKA];

    const int tid  = threadIdx.x;
    const int wid  = tid >> 5, lane = tid & 31;
    const int row0 = blockIdx.y * 128, col0 = blockIdx.x * 128;
    const int wm   = wid >> 2, wn = wid & 3;

    float acc[4][4][4];
    #pragma unroll
    for (int im = 0; im < 4; im++)
        #pragma unroll
        for (int in = 0; in < 4; in++)
            #pragma unroll
            for (int r = 0; r < 4; r++) acc[im][in][r] = 0.f;

    const int lr = tid >> 1, lk = (tid & 1) * 16;
    const __nv_bfloat16* gAh = Ah + (size_t)(row0 + lr) * K + lk;
    const __nv_bfloat16* gAl = Al + (size_t)(row0 + lr) * K + lk;
    const __nv_bfloat16* gBh = Bh + (size_t)(col0 + lr) * K + lk;
    const __nv_bfloat16* gBl = Bl + (size_t)(col0 + lr) * K + lk;
    __nv_bfloat16* pAh = sAh + lr * SKA + lk;
    __nv_bfloat16* pAl = sAl + lr * SKA + lk;
    __nv_bfloat16* pBh = sBh + lr * SKA + lk;
    __nv_bfloat16* pBl = sBl + lr * SKA + lk;

    const uint32_t uAh = smem_u32(sAh), uAl = smem_u32(sAl);
    const uint32_t uBh = smem_u32(sBh), uBl = smem_u32(sBl);
    const int aRow = wm * 64 + (lane & 15);
    const int aCol = (lane >> 4) * 8;
    const int bRow = wn * 32 + ((lane >> 3) & 1) * 8 + (lane & 7);
    const int bCol = (lane >> 4) * 8;

    for (int k0 = 0; k0 < K; k0 += 32) {
        __syncthreads();
        *(uint4*)(pAh)     = *(const uint4*)(gAh);
        *(uint4*)(pAh + 8) = *(const uint4*)(gAh + 8);
        *(uint4*)(pAl)     = *(const uint4*)(gAl);
        *(uint4*)(pAl + 8) = *(const uint4*)(gAl + 8);
        *(uint4*)(pBh)     = *(const uint4*)(gBh);
        *(uint4*)(pBh + 8) = *(const uint4*)(gBh + 8);
        *(uint4*)(pBl)     = *(const uint4*)(gBl);
        *(uint4*)(pBl + 8) = *(const uint4*)(gBl + 8);
        gAh += 32; gAl += 32; gBh += 32; gBl += 32;
        __syncthreads();

        #pragma unroll
        for (int ks = 0; ks < 32; ks += 16) {
            uint32_t afh[4][4], afl[4][4];
            #pragma unroll
            for (int im = 0; im < 4; im++) {
                uint32_t off = ((aRow + im * 16) * SKA + ks + aCol) * 2;
                ldsm4(afh[im][0], afh[im][1], afh[im][2], afh[im][3], uAh + off);
                ldsm4(afl[im][0], afl[im][1], afl[im][2], afl[im][3], uAl + off);
            }
            uint32_t bfh[2][4], bfl[2][4];
            #pragma unroll
            for (int p = 0; p < 2; p++) {
                uint32_t off = ((bRow + p * 16) * SKA + ks + bCol) * 2;
                ldsm4(bfh[p][0], bfh[p][1], bfh[p][2], bfh[p][3], uBh + off);
                ldsm4(bfl[p][0], bfl[p][1], bfl[p][2], bfl[p][3], uBl + off);
            }
            #pragma unroll
            for (int im = 0; im < 4; im++) {
                #pragma unroll
                for (int in = 0; in < 4; in++) {
                    const int p = in >> 1, q = in & 1;
                    uint32_t bh0 = bfh[p][q], bh1 = bfh[p][2 + q];
                    uint32_t bl0 = bfl[p][q], bl1 = bfl[p][2 + q];
                    mma16816(acc[im][in], afh[im], bh0, bh1);
                    mma16816(acc[im][in], afh[im], bl0, bl1);
                    mma16816(acc[im][in], afl[im], bh0, bh1);
                }
            }
        }
    }

    const int cr = lane >> 2, cc = (lane & 3) * 2;
    #pragma unroll
    for (int im = 0; im < 4; im++) {
        #pragma unroll
        for (int in = 0; in < 4; in++) {
            int gm = row0 + wm * 64 + im * 16 + cr;
            int gn = col0 + wn * 32 + in * 8 + cc;
            float2 v0 = make_float2(acc[im][in][0], acc[im][in][1]);
            float2 v1 = make_float2(acc[im][in][2], acc[im][in][3]);
            *(float2*)(C + (size_t)gm * N + gn)       = v0;
            *(float2*)(C + (size_t)(gm + 8) * N + gn) = v1;
        }
    }
}

// ---------------- fp32 -> bf16 hi/lo split -----------------------------------
__global__ void split_bf16(const float* __restrict__ in,
                           __nv_bfloat16* __restrict__ hi,
                           __nv_bfloat16* __restrict__ lo, int n)
{
    int i = blockIdx.x * 256 + threadIdx.x;
    if (i < n) {
        float a = in[i];
        __nv_bfloat16 h = __float2bfloat16(a);
        hi[i] = h;
        lo[i] = __float2bfloat16(a - __bfloat162float(h));
    }
}

// ---------------- transpose + split: W[K][N] -> WT hi/lo [rows][K] -----------
// Writes full 32-row tiles; rows >= N get zeros (safe padding).
__global__ void tsplit_kernel(const float* __restrict__ W,
                              __nv_bfloat16* __restrict__ hi,
                              __nv_bfloat16* __restrict__ lo,
                              int K, int N)
{
    __shared__ float t[32][33];
    int kb = blockIdx.x * 32, nb = blockIdx.y * 32;
    int tx = threadIdx.x, ty = threadIdx.y;
    #pragma unroll
    for (int i = 0; i < 4; i++) {
        int k = kb + ty + i * 8;
        int n = nb + tx;
        t[ty + i * 8][tx] = (n < N) ? W[(size_t)k * N + n] : 0.f;
    }
    __syncthreads();
    #pragma unroll
    for (int i = 0; i < 4; i++) {
        int n = nb + ty + i * 8;
        int k = kb + tx;
        float a = t[tx][ty + i * 8];
        __nv_bfloat16 h = __float2bfloat16(a);
        hi[(size_t)n * K + k] = h;
        lo[(size_t)n * K + k] = __float2bfloat16(a - __bfloat162float(h));
    }
}

// ---------------- unpack fa/ga/beta from fused qkv output --------------------
// src row stride NQKV; cols [0:128)=fa, [128:256)=ga, [256:272)=beta-raw
__global__ void unpack_fga(const float* __restrict__ src,
                           __nv_bfloat16* __restrict__ fah, __nv_bfloat16* __restrict__ fal,
                           __nv_bfloat16* __restrict__ gah, __nv_bfloat16* __restrict__ gal,
                           float* __restrict__ beta)
{
    int i = blockIdx.x * 256 + threadIdx.x;
    if (i >= BSN * 384) return;
    int m = i / 384, c = i - m * 384;
    float v = src[(size_t)m * NQKV + c];
    if (c < 128) {
        __nv_bfloat16 h = __float2bfloat16(v);
        fah[m * 128 + c] = h;
        fal[m * 128 + c] = __float2bfloat16(v - __bfloat162float(h));
    } else if (c < 256) {
        __nv_bfloat16 h = __float2bfloat16(v);
        gah[m * 128 + c - 128] = h;
        gal[m * 128 + c - 128] = __float2bfloat16(v - __bfloat162float(h));
    } else if (c < 272) {
        beta[m * 16 + (c - 256)] = 1.f / (1.f + __expf(-v));
    }
}

// ---------------- causal depthwise conv (KC=4) + SiLU + optional l2norm ------
// lin has row stride NQKV, channel offset coff.
__global__ void conv_silu_kernel(const float* __restrict__ lin, int coff,
                                 const float* __restrict__ kern,
                                 float* __restrict__ outp, int do_l2)
{
    int tok = blockIdx.x;
    int h   = blockIdx.y;
    int d   = threadIdx.x;
    int t   = tok & (SS - 1);
    int c   = h * DD + d;

    float acc = 0.f;
    #pragma unroll
    for (int j = 0; j < 4; j++) {
        int tt = t - 3 + j;
        if (tt >= 0) acc += lin[(size_t)(tok - 3 + j) * NQKV + coff + c] * kern[j * HD + c];
    }
    float y = acc / (1.f + __expf(-acc));

    if (do_l2) {
        float ss = y * y;
        #pragma unroll
        for (int off = 16; off; off >>= 1) ss += __shfl_xor_sync(0xffffffffu, ss, off);
        __shared__ float wsum[4];
        if ((d & 31) == 0) wsum[d >> 5] = ss;
        __syncthreads();
        float tot = wsum[0] + wsum[1] + wsum[2] + wsum[3];
        y *= rsqrtf(tot + 1e-6f);
    }
    outp[(size_t)tok * HD + c] = y;
}

// ---------------- g = -exp(A_log[h]) * softplus(g_lin + dt_bias) -------------
__global__ void g_transform_kernel(float* __restrict__ g,
                                   const float* __restrict__ A_log,
                                   const float* __restrict__ dt_bias)
{
    int i = blockIdx.x * 256 + threadIdx.x;
    if (i >= BSN * HD) return;
    int c = i & (HD - 1);
    float xv = g[i] + dt_bias[c];
    float sp = (xv > 20.f) ? xv : log1pf(__expf(xv));
    g[i] = -__expf(A_log[c >> 7]) * sp;
}

// ---------------- per-chunk precompute ---------------------------------------
__global__ __launch_bounds__(256) void precompute_kernel(
    const float* __restrict__ qv, const float* __restrict__ kv,
    const float* __restrict__ gv, const float* __restrict__ betav,
    float* __restrict__ w_g, float* __restrict__ tf_g,
    float* __restrict__ attn_g, float* __restrict__ qg_g,
    float* __restrict__ kt_g, float* __restrict__ egl_g)
{
    const int n  = blockIdx.x;
    const int bh = blockIdx.y;
    const int b  = bh >> 4;
    const int h  = bh & 15;
    const int tid = threadIdx.x;
    const int chIdx = bh * NCH + n;
    const size_t baseTok = (size_t)b * SS + n * CCH;

    extern __shared__ float sm[];
    float* sk = sm;                    // 8192
    float* sg = sm + 8192;             // 8192
    float* sA = sm + 16384;            // 64*65
    float* sT = sA + 64 * 65;          // 64*65
    float* sb = sT + 64 * 65;          // 64

    for (int l = tid; l < 8192; l += 256) {
        int i = l >> 7, d = l & 127;
        size_t gi = ((baseTok + i) * HH + h) * DD + d;
        sk[l] = kv[gi];
        sg[l] = gv[gi];
    }
    if (tid < 64) sb[tid] = betav[(baseTok + tid) * HH + h];
    __syncthreads();

    if (tid < 128) {
        float acc = sg[tid];
        for (int i = 1; i < 64; i++) { acc += sg[i * 128 + tid]; sg[i * 128 + tid] = acc; }
    }
    for (int l = tid; l < 4096; l += 256) {
        int i2 = l >> 6, j2 = l & 63;
        if (j2 > i2) attn_g[(size_t)chIdx * 4096 + l] = 0.f;
    }
    __syncthreads();

    {
        const int i   = tid >> 2;
        const int cch = tid & 3;
        const int d0  = cch * 32;
        float qreg[32], kreg[32], greg[32];
        const float* qp = qv + ((baseTok + i) * HH + h) * DD + d0;
        #pragma unroll
        for (int d = 0; d < 32; d++) {
            qreg[d] = __ldg(qp + d);
            kreg[d] = sk[i * 128 + d0 + d];
            greg[d] = sg[i * 128 + d0 + d];
        }
        const unsigned lane = tid & 31;
        const unsigned gmask = 0xFu << (lane & ~3u);
        const size_t aoff = (size_t)chIdx * 4096 + i * 64;
        for (int j = 0; j <= i; j++) {
            float aA = 0.f, aQ = 0.f;
            const float* skj = sk + j * 128 + d0;
            const float* sgj = sg + j * 128 + d0;
            #pragma unroll
            for (int d = 0; d < 32; d++) {
                float e  = __expf(greg[d] - sgj[d]);
                float kk = e * skj[d];
                aQ += kk * qreg[d];
                aA += kk * kreg[d];
            }
            aA += __shfl_down_sync(gmask, aA, 1, 4);
            aA += __shfl_down_sync(gmask, aA, 2, 4);
            aQ += __shfl_down_sync(gmask, aQ, 1, 4);
            aQ += __shfl_down_sync(gmask, aQ, 2, 4);
            if (cch == 0) {
                attn_g[aoff + j] = aQ * QSCALE;
                if (j < i) sA[i * 65 + j] = aA * sb[i];
            }
        }
    }
    __syncthreads();

    for (int l = tid; l < 64 * 65; l += 256) sT[l] = 0.f;
    __syncthreads();
    if (tid < 64) sT[tid * 65 + tid] = 1.f;
    __syncthreads();
    for (int ii = 1; ii < 64; ii++) {
        if (tid < ii) {
            int j = tid;
            float s = sA[ii * 65 + j];
            for (int m = j + 1; m < ii; m++) s += sA[ii * 65 + m] * sT[m * 65 + j];
            sT[ii * 65 + j] = -s;
        }
        __syncthreads();
    }
    for (int l = tid; l < 4096; l += 256) {
        int i2 = l >> 6, j2 = l & 63;
        sT[i2 * 65 + j2] *= sb[j2];
    }
    __syncthreads();
    for (int l = tid; l < 4096; l += 256)
        tf_g[(size_t)chIdx * 4096 + l] = sT[(l >> 6) * 65 + (l & 63)];

    if (tid < 128) egl_g[(size_t)chIdx * 128 + tid] = __expf(sg[63 * 128 + tid]);
    for (int l = tid; l < 8192; l += 256) {
        int i2 = l >> 7, d = l & 127;
        float gl = sg[63 * 128 + d];
        float gi = sg[l];
        kt_g[(size_t)chIdx * 8192 + l] = sk[l] * __expf(gl - gi);
        size_t qidx = ((baseTok + i2) * HH + h) * DD + d;
        qg_g[(size_t)chIdx * 8192 + l] = __ldg(qv + qidx) * __expf(gi) * QSCALE;
    }
    __syncthreads();
    for (int l = tid; l < 8192; l += 256) sk[l] *= __expf(sg[l]);
    __syncthreads();

    {
        const int ig  = tid >> 4;
        const int dg  = tid & 15;
        const int i0  = ig * 4;
        const int dd0 = dg * 8;
        float acc[4][8];
        #pragma unroll
        for (int r = 0; r < 4; r++)
            #pragma unroll
            for (int d = 0; d < 8; d++) acc[r][d] = 0.f;
        for (int j = 0; j < 64; j++) {
            float t0 = sT[(i0 + 0) * 65 + j];
            float t1 = sT[(i0 + 1) * 65 + j];
            float t2 = sT[(i0 + 2) * 65 + j];
            float t3 = sT[(i0 + 3) * 65 + j];
            #pragma unroll
            for (int d = 0; d < 8; d++) {
                float kvv = sk[j * 128 + dd0 + d];
                acc[0][d] += t0 * kvv;
                acc[1][d] += t1 * kvv;
                acc[2][d] += t2 * kvv;
                acc[3][d] += t3 * kvv;
            }
        }
        #pragma unroll
        for (int r = 0; r < 4; r++)
            #pragma unroll
            for (int d = 0; d < 8; d++)
                w_g[(size_t)chIdx * 8192 + (i0 + r) * 128 + dd0 + d] = acc[r][d];
    }
}

// ---------------- sequential chunk scan, split over dv (tiles of 16) ---------
__global__ __launch_bounds__(256) void scan_kernel(
    const float* __restrict__ vv, const float* __restrict__ w_g,
    const float* __restrict__ tf_g, const float* __restrict__ attn_g,
    const float* __restrict__ qg_g, const float* __restrict__ kt_g,
    const float* __restrict__ egl_g, float* __restrict__ core)
{
    const int blk = blockIdx.x;
    const int bh  = blk >> 3;
    const int b   = bh >> 4, h = bh & 15;
    const int e0  = (blk & 7) * 16;
    const int tid = threadIdx.x;
    const int e   = tid & 15;
    const int cb  = tid >> 4;

    extern __shared__ float sm[];
    float* sS = sm;            // 128*16
    float* sV = sm + 2048;     // 64*16
    float* sU = sm + 3072;     // 64*16
    float* sM = sm + 4096;     // 64*64
    float* sW = sm + 8192;     // 64*128
    float* sE = sm + 16384;    // 128

    for (int l = tid; l < 2048; l += 256) sS[l] = 0.f;

    for (int n = 0; n < NCH; n++) {
        const size_t ch = (size_t)bh * NCH + n;
        const size_t tokBase = (size_t)b * SS + n * CCH;
        __syncthreads();
        for (int l = tid; l < 1024; l += 256) {
            int c = l >> 4, ee = l & 15;
            sV[l] = vv[((tokBase + c) * HH + h) * DD + e0 + ee];
        }
        for (int l = tid; l < 4096; l += 256) sM[l] = tf_g[ch * 4096 + l];
        __syncthreads();
        float a0 = 0, a1 = 0, a2 = 0, a3 = 0;
        for (int j = 0; j < 64; j++) {
            float vj = sV[j * 16 + e];
            a0 += sM[(cb     ) * 64 + j] * vj;
            a1 += sM[(cb + 16) * 64 + j] * vj;
            a2 += sM[(cb + 32) * 64 + j] * vj;
            a3 += sM[(cb + 48) * 64 + j] * vj;
        }
        __syncthreads();
        for (int l = tid; l < 8192; l += 256) sW[l] = w_g[ch * 8192 + l];
        __syncthreads();
        for (int d = 0; d < 128; d++) {
            float sd = sS[d * 16 + e];
            a0 -= sW[(cb     ) * 128 + d] * sd;
            a1 -= sW[(cb + 16) * 128 + d] * sd;
            a2 -= sW[(cb + 32) * 128 + d] * sd;
            a3 -= sW[(cb + 48) * 128 + d] * sd;
        }
        sU[(cb     ) * 16 + e] = a0;
        sU[(cb + 16) * 16 + e] = a1;
        sU[(cb + 32) * 16 + e] = a2;
        sU[(cb + 48) * 16 + e] = a3;
        __syncthreads();
        for (int l = tid; l < 4096; l += 256) sM[l] = attn_g[ch * 4096 + l];
        for (int l = tid; l < 8192; l += 256) sW[l] = qg_g[ch * 8192 + l];
        __syncthreads();
        float o0 = 0, o1 = 0, o2 = 0, o3 = 0;
        for (int j = 0; j < 64; j++) {
            float uj = sU[j * 16 + e];
            o0 += sM[(cb     ) * 64 + j] * uj;
            o1 += sM[(cb + 16) * 64 + j] * uj;
            o2 += sM[(cb + 32) * 64 + j] * uj;
            o3 += sM[(cb + 48) * 64 + j] * uj;
        }
        for (int d = 0; d < 128; d++) {
            float sd = sS[d * 16 + e];
            o0 += sW[(cb     ) * 128 + d] * sd;
            o1 += sW[(cb + 16) * 128 + d] * sd;
            o2 += sW[(cb + 32) * 128 + d] * sd;
            o3 += sW[(cb + 48) * 128 + d] * sd;
        }
        core[((tokBase + cb     ) * HH + h) * DD + e0 + e] = o0;
        core[((tokBase + cb + 16) * HH + h) * DD + e0 + e] = o1;
        core[((tokBase + cb + 32) * HH + h) * DD + e0 + e] = o2;
        core[((tokBase + cb + 48) * HH + h) * DD + e0 + e] = o3;
        __syncthreads();
        for (int l = tid; l < 8192; l += 256) sW[l] = kt_g[ch * 8192 + l];
        if (tid < 128) sE[tid] = egl_g[ch * 128 + tid];
        __syncthreads();
        float sacc[8];
        #pragma unroll
        for (int r = 0; r < 8; r++) sacc[r] = sE[cb + 16 * r] * sS[(cb + 16 * r) * 16 + e];
        for (int c = 0; c < 64; c++) {
            float u = sU[c * 16 + e];
            #pragma unroll
            for (int r = 0; r < 8; r++) sacc[r] += sW[c * 128 + cb + 16 * r] * u;
        }
        #pragma unroll
        for (int r = 0; r < 8; r++) sS[(cb + 16 * r) * 16 + e] = sacc[r];
    }
}

// ---------------- RMS norm * sigmoid(gate + bgb) -> bf16 hi/lo ---------------
__global__ void rmsgate_kernel(const float* __restrict__ core,
                               const float* __restrict__ gate,
                               const float* __restrict__ bgb,
                               const float* __restrict__ rms_scale,
                               __nv_bfloat16* __restrict__ yh,
                               __nv_bfloat16* __restrict__ yl)
{
    int tok = blockIdx.x, h = blockIdx.y, d = threadIdx.x;
    int c = h * DD + d;
    size_t i = (size_t)tok * HD + c;
    float cf = core[i];
    float ss = cf * cf;
    #pragma unroll
    for (int off = 16; off; off >>= 1) ss += __shfl_xor_sync(0xffffffffu, ss, off);
    __shared__ float ws[4];
    if ((d & 31) == 0) ws[d >> 5] = ss;
    __syncthreads();
    float tot = ws[0] + ws[1] + ws[2] + ws[3];
    float normed = cf * rsqrtf(tot * (1.f / 128.f) + 1e-5f) * rms_scale[d];
    float gt = gate[i] + bgb[c];
    float o = normed / (1.f + __expf(-gt));
    __nv_bfloat16 hh = __float2bfloat16(o);
    yh[i] = hh;
    yl[i] = __float2bfloat16(o - __bfloat162float(hh));
}

// ---------------- launch ------------------------------------------------------
extern "C" void kernel_launch(void* const* d_in, const int* in_sizes, int n_in,
                              void* d_out, int out_size)
{
    const float* x      = (const float*)d_in[0];
    const float* Wq     = (const float*)d_in[1];
    const float* Wk     = (const float*)d_in[2];
    const float* Wv     = (const float*)d_in[3];
    const float* convq  = (const float*)d_in[4];
    const float* convk  = (const float*)d_in[5];
    const float* convv  = (const float*)d_in[6];
    const float* Wb     = (const float*)d_in[7];
    const float* Wfa    = (const float*)d_in[8];
    const float* Wfb    = (const float*)d_in[9];
    const float* Wga    = (const float*)d_in[10];
    const float* Wgb    = (const float*)d_in[11];
    const float* bgb    = (const float*)d_in[12];
    const float* A_log  = (const float*)d_in[13];
    const float* dt_bias= (const float*)d_in[14];
    const float* rms_sc = (const float*)d_in[15];
    const float* Wo     = (const float*)d_in[16];
    float* outp = (float*)d_out;

    float *qkv, *qb, *kb, *vb, *gb, *gate, *core, *beta;
    float *wg, *tfg, *attng, *qgg, *ktg, *eglg;
    __nv_bfloat16 *xh, *xl, *yh, *yl, *fah, *fal, *gah, *gal;
    __nv_bfloat16 *WxTh, *WxTl, *WoTh, *WoTl, *WfbTh, *WfbTl, *WgbTh, *WgbTl;

    cudaGetSymbolAddress((void**)&qkv,  d_qkv);
    cudaGetSymbolAddress((void**)&qb,   d_qb);
    cudaGetSymbolAddress((void**)&kb,   d_kb);
    cudaGetSymbolAddress((void**)&vb,   d_vb);
    cudaGetSymbolAddress((void**)&gb,   d_gb);
    cudaGetSymbolAddress((void**)&gate, d_gate);
    cudaGetSymbolAddress((void**)&core, d_core);
    cudaGetSymbolAddress((void**)&beta, d_beta);
    cudaGetSymbolAddress((void**)&wg,   d_w);
    cudaGetSymbolAddress((void**)&tfg,  d_tf);
    cudaGetSymbolAddress((void**)&attng,d_attn);
    cudaGetSymbolAddress((void**)&qgg,  d_qg);
    cudaGetSymbolAddress((void**)&ktg,  d_kt);
    cudaGetSymbolAddress((void**)&eglg, d_egl);
    cudaGetSymbolAddress((void**)&xh, d_xh);   cudaGetSymbolAddress((void**)&xl, d_xl);
    cudaGetSymbolAddress((void**)&yh, d_yh);   cudaGetSymbolAddress((void**)&yl, d_yl);
    cudaGetSymbolAddress((void**)&fah, d_fah); cudaGetSymbolAddress((void**)&fal, d_fal);
    cudaGetSymbolAddress((void**)&gah, d_gah); cudaGetSymbolAddress((void**)&gal, d_gal);
    cudaGetSymbolAddress((void**)&WxTh, d_WxTh); cudaGetSymbolAddress((void**)&WxTl, d_WxTl);
    cudaGetSymbolAddress((void**)&WoTh, d_WoTh); cudaGetSymbolAddress((void**)&WoTl, d_WoTl);
    cudaGetSymbolAddress((void**)&WfbTh, d_WfbTh); cudaGetSymbolAddress((void**)&WfbTl, d_WfbTl);
    cudaGetSymbolAddress((void**)&WgbTh, d_WgbTh); cudaGetSymbolAddress((void**)&WgbTl, d_WgbTl);

    const size_t preSmem  = 24768 * sizeof(float);
    const size_t scanSmem = 16512 * sizeof(float);
    cudaFuncSetAttribute(precompute_kernel, cudaFuncAttributeMaxDynamicSharedMemorySize, (int)preSmem);
    cudaFuncSetAttribute(scan_kernel,       cudaFuncAttributeMaxDynamicSharedMemorySize, (int)scanSmem);

    dim3 blk256(256);
    dim3 tblk(32, 8);

    // weight staging into the fused WxT: rows [0:2048)=Wq, [2048:4096)=Wk,
    // [4096:6144)=Wv, [6144:6272)=Wfa, [6272:6400)=Wga, [6400:6528)=Wb(pad 0)
    split_bf16<<<(BSN * HIDN) / 256, blk256>>>(x, xh, xl, BSN * HIDN);
    tsplit_kernel<<<dim3(HIDN / 32, HD / 32), tblk>>>(Wq, WxTh,               WxTl,               HIDN, HD);
    tsplit_kernel<<<dim3(HIDN / 32, HD / 32), tblk>>>(Wk, WxTh + 2048 * HIDN, WxTl + 2048 * HIDN, HIDN, HD);
    tsplit_kernel<<<dim3(HIDN / 32, HD / 32), tblk>>>(Wv, WxTh + 4096 * HIDN, WxTl + 4096 * HIDN, HIDN, HD);
    tsplit_kernel<<<dim3(HIDN / 32, 4), tblk>>>(Wfa, WxTh + 6144 * HIDN, WxTl + 6144 * HIDN, HIDN, DD);
    tsplit_kernel<<<dim3(HIDN / 32, 4), tblk>>>(Wga, WxTh + 6272 * HIDN, WxTl + 6272 * HIDN, HIDN, DD);
    tsplit_kernel<<<dim3(HIDN / 32, 4), tblk>>>(Wb,  WxTh + 6400 * HIDN, WxTl + 6400 * HIDN, HIDN, HH);

    // ONE fused x-projection GEMM: N=6528, grid 3264 CTAs (11.03 waves)
    tc_gemm<<<dim3(NQKV / 128, 64), 256>>>(xh, xl, WxTh, WxTl, qkv, BSN, NQKV, HIDN);

    unpack_fga<<<(BSN * 384) / 256, blk256>>>(qkv + 6144, fah, fal, gah, gal, beta);

    // conv + silu (+ l2norm for q,k), reading strided from qkv
    conv_silu_kernel<<<dim3(BSN, HH), 128>>>(qkv, 0,    convq, qb, 1);
    conv_silu_kernel<<<dim3(BSN, HH), 128>>>(qkv, 2048, convk, kb, 1);
    conv_silu_kernel<<<dim3(BSN, HH), 128>>>(qkv, 4096, convv, vb, 0);

    // second-stage projections
    tsplit_kernel<<<dim3(HD / 32, HIDN / 32), tblk>>>(Wo, WoTh, WoTl, HD, HIDN);
    tsplit_kernel<<<dim3(DD / 32, HD / 32), tblk>>>(Wfb, WfbTh, WfbTl, DD, HD);
    tsplit_kernel<<<dim3(DD / 32, HD / 32), tblk>>>(Wgb, WgbTh, WgbTl, DD, HD);
    tc_gemm<<<dim3(16, 64), 256>>>(fah, fal, WfbTh, WfbTl, gb, BSN, HD, DD);
    tc_gemm<<<dim3(16, 64), 256>>>(gah, gal, WgbTh, WgbTl, gate, BSN, HD, DD);
    g_transform_kernel<<<(BSN * HD) / 256, blk256>>>(gb, A_log, dt_bias);

    // chunked delta rule
    precompute_kernel<<<dim3(NCH, BB * HH), blk256, preSmem>>>(
        qb, kb, gb, beta, wg, tfg, attng, qgg, ktg, eglg);
    scan_kernel<<<dim3(BB * HH * 8), blk256, scanSmem>>>(
        vb, wg, tfg, attng, qgg, ktg, eglg, core);

    // rmsnorm * gate -> bf16 hi/lo, final projection
    rmsgate_kernel<<<dim3(BSN, HH), 128>>>(core, gate, bgb, rms_sc, yh, yl);
    tc_gemm<<<dim3(16, 64), 256>>>(yh, yl, WoTh, WoTl, outp, BSN, HIDN, HD);
}